// round 15
// baseline (speedup 1.0000x reference)
#include <cuda_runtime.h>
#include <cuda_bf16.h>
#include <math.h>
#include <float.h>

#define BB 4
#define LL 4096
#define DD 256
#define SS 32
#define TOPK 8
#define D2 512   // 2*DD (interleaved real/imag)

// ---------------- scratch (__device__ globals; no allocation allowed) ----------------
__device__ float  g_phase[BB*LL];
__device__ float  g_avgmag[BB*LL];
__device__ float  g_sal[BB*LL];
__device__ int    g_spst[BB*SS];
__device__ int    g_spen[BB*SS];
__device__ float  g_event[BB*SS*D2];
__device__ double g_kmag[BB*SS];
__device__ float  g_Cf[(size_t)BB*D2*SS];  // [b][j][s] fp32 (computed in fp64)
__device__ float  g_WqT[D2*D2];   // packed complex weight, transposed: [j][o] = W2[o][j]
__device__ float  g_WkT[D2*D2];
__device__ float  g_WvT[D2*D2];

__device__ __forceinline__ float to_tf32(float x) {
    unsigned u;
    asm("cvt.rna.tf32.f32 %0, %1;" : "=r"(u) : "f"(x));
    return __uint_as_float(u);
}

// ---------------- K0: pack complex weight into real [512x512], stored transposed ----------------
__global__ void k_pack(const float* __restrict__ wr, const float* __restrict__ wi,
                       float* __restrict__ dstT) {
    int idx = blockIdx.x * blockDim.x + threadIdx.x;   // 512*512 total
    int o = idx >> 9, j = idx & 511;
    int d = o >> 1, cr = o & 1, e = j >> 1, ci = j & 1;
    float R = wr[d*DD + e], I = wi[d*DD + e];
    float w = (cr == 0) ? ((ci == 0) ? R : -I)
                        : ((ci == 0) ? I :  R);
    dstT[(size_t)j * D2 + o] = w;
}

// ---------------- K1: per-position salience dot + avg magnitude (fp64 accum) ----------------
__global__ void k_sal1(const float* __restrict__ z, const float* __restrict__ swr,
                       const float* __restrict__ swi) {
    int p = blockIdx.x, t = threadIdx.x;   // 128 threads
    const float* zp = z + (size_t)p * D2;
    double orr = 0.0, oii = 0.0, mg = 0.0;
    for (int d = t; d < DD; d += 128) {
        float zr = zp[2*d], zi = zp[2*d+1];
        float a = swr[d], b = swi[d];
        orr += (double)zr*a - (double)zi*b;
        oii += (double)zr*b + (double)zi*a;
        mg  += sqrt((double)zr*zr + (double)zi*zi);
    }
    __shared__ double s0[128], s1[128], s2[128];
    s0[t] = orr; s1[t] = oii; s2[t] = mg; __syncthreads();
    for (int off = 64; off; off >>= 1) {
        if (t < off) { s0[t] += s0[t+off]; s1[t] += s1[t+off]; s2[t] += s2[t+off]; }
        __syncthreads();
    }
    if (t == 0) {
        g_phase[p]  = (float)sqrt(s0[0]*s0[0] + s1[0]*s1[0]);
        g_avgmag[p] = (float)(s2[0] * (1.0/256.0));
    }
}

// ---------------- K2: local mean (5-tap, zero-pad) + sigmoid ----------------
__global__ void k_sal2(const float* __restrict__ bias, const float* __restrict__ nov,
                       float* __restrict__ out_sal) {
    int p = blockIdx.x * blockDim.x + threadIdx.x;
    if (p >= BB*LL) return;
    int b = p >> 12, l = p & (LL-1);
    double lm = 0.0;
    #pragma unroll
    for (int j = -2; j <= 2; j++) {
        int q = l + j;
        if (q >= 0 && q < LL) lm += (double)g_avgmag[(b << 12) + q];
    }
    lm *= 0.2;
    double x = (double)g_phase[p] + ((double)g_avgmag[p] - lm) * (double)nov[0] + (double)bias[0];
    float s = (float)(1.0 / (1.0 + exp(-x)));
    g_sal[p] = s;
    out_sal[p] = s;
}

// ---------------- K3: per-batch span scan (exact cumsum of starts) ----------------
__global__ void k_scan(const float* __restrict__ slot_mask, float* __restrict__ out_mask) {
    int b = blockIdx.x, t = threadIdx.x;   // 1024 threads
    __shared__ int sA[LL];
    __shared__ int sP[1024];
    __shared__ int s_n;
    if (t < SS) { g_spst[b*SS + t] = -1; g_spen[b*SS + t] = -1; }
    const float* sb = g_sal + b * LL;
    for (int i = 0; i < 4; i++) { int l = t*4 + i; sA[l] = (sb[l] > 0.5f); }
    __syncthreads();
    int part = 0;
    for (int i = 0; i < 4; i++) {
        int l = t*4 + i;
        int a = sA[l], pr = l ? sA[l-1] : 0;
        part += (a && !pr);
    }
    sP[t] = part; __syncthreads();
    for (int off = 1; off < 1024; off <<= 1) {
        int v = (t >= off) ? sP[t - off] : 0;
        __syncthreads();
        sP[t] += v;
        __syncthreads();
    }
    int run = sP[t] - part;   // exclusive prefix of start count
    for (int i = 0; i < 4; i++) {
        int l = t*4 + i;
        int a = sA[l], pr = l ? sA[l-1] : 0;
        int st = (a && !pr);
        if (st) run++;
        int si = run - 1;
        if (a && si >= 0 && si < SS) {
            if (st) g_spst[b*SS + si] = l;
            int nx = (l < LL-1) ? sA[l+1] : 0;
            if (!nx) g_spen[b*SS + si] = l + 1;
        }
    }
    __syncthreads();
    if (t == 0) s_n = sP[1023];
    __syncthreads();
    if (t < SS) {
        int n = s_n; if (n > SS) n = SS;
        float ev = (t < n) ? 1.f : 0.f;
        out_mask[b*SS + t] = fminf(slot_mask[b*SS + t] + ev, 1.f);
    }
}

// ---------------- K4: salience-weighted pooling per span (fp64 accum) ----------------
__global__ void k_pool(const float* __restrict__ z) {
    int blk = blockIdx.x;            // B*S
    int b = blk >> 5, t = threadIdx.x;   // 256 threads
    int st = g_spst[blk];
    if (st < 0) return;
    int en = g_spen[blk];
    const float* sb = g_sal + b * LL;
    double a0 = 0.0, a1 = 0.0, ws = 0.0;
    for (int l = st; l < en; l++) {
        double w = (double)sb[l];
        const float* zp = z + ((size_t)(b*LL + l)) * D2;
        a0 += w * (double)zp[t];
        a1 += w * (double)zp[t + 256];
        ws += w;
    }
    double inv = 1.0 / fmax(ws, 1e-8);
    g_event[(size_t)blk*D2 + t]       = (float)(a0 * inv);
    g_event[(size_t)blk*D2 + t + 256] = (float)(a1 * inv);
}

// ---------------- K5: event key/value projections + blend + k_mag (fp64 accum) ----------------
__global__ void k_proj(const float* __restrict__ slotk, const float* __restrict__ slotv,
                       float* __restrict__ outk, float* __restrict__ outv) {
    int blk = blockIdx.x, t = threadIdx.x;   // 256 threads
    __shared__ float  ev[D2];
    __shared__ double red[256];
    bool valid = (g_spst[blk] >= 0);
    if (valid) {
        ev[t]       = g_event[(size_t)blk*D2 + t];
        ev[t + 256] = g_event[(size_t)blk*D2 + t + 256];
    }
    __syncthreads();
    float k1, k2, v1, v2;
    if (valid) {
        double ka = 0.0, kb = 0.0, va = 0.0, vb = 0.0;
        for (int j = 0; j < D2; j++) {
            double e = (double)ev[j];
            const float* wk = g_WkT + (size_t)j * D2;
            const float* wv = g_WvT + (size_t)j * D2;
            ka += e * (double)wk[t]; kb += e * (double)wk[t + 256];
            va += e * (double)wv[t]; vb += e * (double)wv[t + 256];
        }
        k1 = (float)ka; k2 = (float)kb; v1 = (float)va; v2 = (float)vb;
    } else {
        k1 = slotk[(size_t)blk*D2 + t]; k2 = slotk[(size_t)blk*D2 + t + 256];
        v1 = slotv[(size_t)blk*D2 + t]; v2 = slotv[(size_t)blk*D2 + t + 256];
    }
    outk[(size_t)blk*D2 + t] = k1; outk[(size_t)blk*D2 + t + 256] = k2;
    outv[(size_t)blk*D2 + t] = v1; outv[(size_t)blk*D2 + t + 256] = v2;
    red[t] = (double)k1*k1 + (double)k2*k2; __syncthreads();
    for (int off = 128; off; off >>= 1) {
        if (t < off) red[t] += red[t + off];
        __syncthreads();
    }
    if (t == 0) g_kmag[blk] = sqrt(red[0] + 1e-8);
}

// ---------------- K5b: C[b][j][s] = sum_o WqT[j][o] * newk[b][s][o] (fp64 -> fp32 store) ----
__global__ void k_C(const float* __restrict__ newk) {
    int blk = blockIdx.x;            // b*SS + s
    int b = blk >> 5, s = blk & 31, t = threadIdx.x;   // 256 threads
    __shared__ float ks[D2];
    ks[t]       = newk[(size_t)blk*D2 + t];
    ks[t + 256] = newk[(size_t)blk*D2 + t + 256];
    __syncthreads();
    #pragma unroll
    for (int jj = 0; jj < 2; jj++) {
        int j = t + jj*256;
        const float* wrow = g_WqT + (size_t)j * D2;
        double a0 = 0.0, a1 = 0.0, a2 = 0.0, a3 = 0.0;
        for (int o = 0; o < D2; o += 4) {
            a0 += (double)wrow[o+0] * (double)ks[o+0];
            a1 += (double)wrow[o+1] * (double)ks[o+1];
            a2 += (double)wrow[o+2] * (double)ks[o+2];
            a3 += (double)wrow[o+3] * (double)ks[o+3];
        }
        g_Cf[((size_t)b*D2 + j)*SS + s] = (float)((a0+a1)+(a2+a3));
    }
}

// ---------------- K6: tf32-mma qmag-GEMM + shared-load chunked-dot attention + RMS ----
// dyn smem layout (floats):
//   As   [16][40]    @ 0       (tf32-rounded z chunk, k-major, padded stride 40)
//   Bs   [16][520]   @ 640     (tf32-rounded WqT chunk, padded stride 520)
//   psum [32][17]    @ 8960    (row sum-of-squares partials)
//   Vs   [32][513]   @ 9504
//   gam  [256]       @ 25920
//   mask [32]        @ 26176
#define SM_AS    0
#define SM_BS    640
#define SM_PS    8960
#define SM_VS    9504
#define SM_GAM   25920
#define SM_MSK   26176
#define SM_TOTAL_F 26208

__global__ __launch_bounds__(256, 2) void k_big(const float* __restrict__ z,
                      const float* __restrict__ newv,
                      const float* __restrict__ newmask,
                      const float* __restrict__ gamma, float* __restrict__ out) {
    extern __shared__ float sm[];
    float* As = sm + SM_AS;       // [16][40]
    float* Bs = sm + SM_BS;       // [16][520]
    float* psum = sm + SM_PS;     // [32][17]
    float* Vs = sm + SM_VS;       // [32][513]
    float* gam_s  = sm + SM_GAM;
    float* mask_s = sm + SM_MSK;
    __shared__ double km_s[SS];

    int t = threadIdx.x;                 // 256
    int b = blockIdx.y;
    int row0 = blockIdx.x * 32;          // within batch
    size_t zbase = ((size_t)b*LL + row0) * D2;

    // stage values/mask/kmag for this batch
    for (int e = t; e < SS*D2; e += 256) {
        int s = e >> 9, j = e & 511;
        Vs[s*513 + j] = newv[((size_t)b*SS + s)*D2 + j];
    }
    if (t < SS) { km_s[t] = g_kmag[b*SS + t]; mask_s[t] = newmask[b*SS + t]; }
    gam_s[t] = gamma[t];

    // ---- GEMM (tf32 tensor cores): Q[32 x 512] = Z[32 x 512] @ WqT; only q_mag uses it.
    int lane = t & 31, w = t >> 5;
    int qrow = lane >> 2, tig = lane & 3;     // fragment group id / thread-in-group
    int rt16 = (w & 1) * 16;
    int cbase = (w >> 1) * 128;

    float c[16][4];
    #pragma unroll
    for (int nt = 0; nt < 16; nt++) {
        c[nt][0] = 0.f; c[nt][1] = 0.f; c[nt][2] = 0.f; c[nt][3] = 0.f;
    }

    for (int k0 = 0; k0 < D2; k0 += 16) {
        __syncthreads();
        #pragma unroll
        for (int i = 0; i < 2; i++) {
            int e = t + i*256; int kk = e & 15, r = e >> 4;
            As[kk*40 + r] = to_tf32(z[zbase + (size_t)r*D2 + k0 + kk]);
        }
        #pragma unroll
        for (int i = 0; i < 32; i++) {
            int e = t + i*256; int o = e & 511, kk = e >> 9;
            Bs[kk*520 + o] = to_tf32(g_WqT[(size_t)(k0 + kk)*D2 + o]);
        }
        __syncthreads();
        #pragma unroll
        for (int ks = 0; ks < 16; ks += 8) {
            int kb = ks + tig;
            float a0 = As[kb*40 + rt16 + qrow];
            float a1 = As[kb*40 + rt16 + qrow + 8];
            float a2 = As[(kb+4)*40 + rt16 + qrow];
            float a3 = As[(kb+4)*40 + rt16 + qrow + 8];
            unsigned ua0 = __float_as_uint(a0), ua1 = __float_as_uint(a1);
            unsigned ua2 = __float_as_uint(a2), ua3 = __float_as_uint(a3);
            #pragma unroll
            for (int nt = 0; nt < 16; nt++) {
                float b0 = Bs[kb*520 + cbase + nt*8 + qrow];
                float b1 = Bs[(kb+4)*520 + cbase + nt*8 + qrow];
                asm volatile(
                    "mma.sync.aligned.m16n8k8.row.col.f32.tf32.tf32.f32 "
                    "{%0,%1,%2,%3}, {%4,%5,%6,%7}, {%8,%9}, {%0,%1,%2,%3};"
                    : "+f"(c[nt][0]), "+f"(c[nt][1]), "+f"(c[nt][2]), "+f"(c[nt][3])
                    : "r"(ua0), "r"(ua1), "r"(ua2), "r"(ua3),
                      "r"(__float_as_uint(b0)), "r"(__float_as_uint(b1)));
            }
        }
    }
    __syncthreads();

    // ---- per-thread row sums-of-squares from C fragments ----
    {
        float plo = 0.f, phi = 0.f;
        #pragma unroll
        for (int nt = 0; nt < 16; nt++) {
            plo += c[nt][0]*c[nt][0] + c[nt][1]*c[nt][1];
            phi += c[nt][2]*c[nt][2] + c[nt][3]*c[nt][3];
        }
        int slot = (w >> 1) * 4 + tig;      // 0..15
        psum[(rt16 + qrow)*17 + slot]     = plo;
        psum[(rt16 + qrow + 8)*17 + slot] = phi;
    }
    __syncthreads();

    // ---- attention: warp w owns rows w*4..w*4+3; slot = lane ----
    const float* Cb = g_Cf + (size_t)b*D2*SS;   // [j][s] fp32

    const float* zr0 = z + ((size_t)b*LL + row0 + w*4 + 0) * D2;
    const float* zr1 = z + ((size_t)b*LL + row0 + w*4 + 1) * D2;
    const float* zr2 = z + ((size_t)b*LL + row0 + w*4 + 2) * D2;
    const float* zr3 = z + ((size_t)b*LL + row0 + w*4 + 3) * D2;
    double dot_[4] = {0.0, 0.0, 0.0, 0.0};
    for (int j0 = 0; j0 < D2; j0 += 16) {
        float p0 = 0.f, p1 = 0.f, p2 = 0.f, p3 = 0.f;
        #pragma unroll
        for (int jj = 0; jj < 16; jj++) {
            int j = j0 + jj;
            float cv = Cb[(size_t)j*SS + lane];
            p0 += zr0[j]*cv;
            p1 += zr1[j]*cv;
            p2 += zr2[j]*cv;
            p3 += zr3[j]*cv;
        }
        dot_[0] += (double)p0;
        dot_[1] += (double)p1;
        dot_[2] += (double)p2;
        dot_[3] += (double)p3;
    }

    for (int ri = 0; ri < 4; ri++) {
        int r = w*4 + ri;
        // |q| from psum (fixed-order fp32 sum of 16 partials -> deterministic)
        float qsq = 0.f;
        #pragma unroll
        for (int i = 0; i < 16; i++) qsq += psum[r*17 + i];
        double qmag = sqrt((double)qsq + 1e-8);
        float scored = (float)(dot_[ri] / (qmag * km_s[lane] + 1e-8));
        if (mask_s[lane] == 0.f) scored = -1e9f;
        // top-8 in fp32 (tie -> lower index, matching lax.top_k)
        float sc = scored;
        float bv_[TOPK]; int bi_[TOPK];
        #pragma unroll
        for (int k = 0; k < TOPK; k++) {
            float vv = sc; int vi = lane;
            #pragma unroll
            for (int off = 16; off; off >>= 1) {
                float ov = __shfl_xor_sync(0xffffffffu, vv, off);
                int   oi = __shfl_xor_sync(0xffffffffu, vi, off);
                if (ov > vv || (ov == vv && oi < vi)) { vv = ov; vi = oi; }
            }
            bv_[k] = vv; bi_[k] = vi;
            if (lane == vi) sc = -3.4e38f;
        }
        // softmax over the 8 (fp32)
        float m = bv_[0], se = 0.f, wn[TOPK];
        #pragma unroll
        for (int k = 0; k < TOPK; k++) { float e = expf(bv_[k] - m); wn[k] = e; se += e; }
        float inv = 1.f / se;
        #pragma unroll
        for (int k = 0; k < TOPK; k++) wn[k] *= inv;
        // retrieved + RMS norm
        float ov_[16]; float m2 = 0.f;
        #pragma unroll
        for (int tt = 0; tt < 16; tt++) {
            int j = lane + tt*32;
            float acc = 0.f;
            #pragma unroll
            for (int k = 0; k < TOPK; k++) acc += wn[k] * Vs[bi_[k]*513 + j];
            ov_[tt] = acc; m2 += acc*acc;
        }
        #pragma unroll
        for (int off = 16; off; off >>= 1) m2 += __shfl_xor_sync(0xffffffffu, m2, off);
        float scale = rsqrtf(m2 * (1.f/256.f) + 1e-8f);
        size_t ob = ((size_t)b*LL + row0 + r) * D2;
        #pragma unroll
        for (int tt = 0; tt < 16; tt++) {
            int j = lane + tt*32;
            out[ob + j] = ov_[tt] * gam_s[j >> 1] * scale;
        }
    }
}

// ---------------- launch ----------------
extern "C" void kernel_launch(void* const* d_in, const int* in_sizes, int n_in,
                              void* d_out, int out_size) {
    const float* z      = (const float*)d_in[0];
    const float* slotk  = (const float*)d_in[1];
    const float* slotv  = (const float*)d_in[2];
    const float* slotm  = (const float*)d_in[3];
    const float* salWr  = (const float*)d_in[4];
    const float* salWi  = (const float*)d_in[5];
    const float* bias   = (const float*)d_in[6];
    const float* nov    = (const float*)d_in[7];
    const float* ekWr   = (const float*)d_in[8];
    const float* ekWi   = (const float*)d_in[9];
    const float* evWr   = (const float*)d_in[10];
    const float* evWi   = (const float*)d_in[11];
    const float* rqWr   = (const float*)d_in[12];
    const float* rqWi   = (const float*)d_in[13];
    const float* gamma  = (const float*)d_in[14];

    float* out   = (float*)d_out;
    float* out_o = out;                               // [4,4096,256,2]
    float* out_k = out + (size_t)BB*LL*D2;            // [4,32,256,2]
    float* out_v = out_k + (size_t)BB*SS*D2;
    float* out_m = out_v + (size_t)BB*SS*D2;          // [4,32]
    float* out_s = out_m + (size_t)BB*SS;             // [4,4096]

    float *dWqT, *dWkT, *dWvT;
    cudaGetSymbolAddress((void**)&dWqT, g_WqT);
    cudaGetSymbolAddress((void**)&dWkT, g_WkT);
    cudaGetSymbolAddress((void**)&dWvT, g_WvT);

    k_pack<<<(D2*D2)/256, 256>>>(rqWr, rqWi, dWqT);
    k_pack<<<(D2*D2)/256, 256>>>(ekWr, ekWi, dWkT);
    k_pack<<<(D2*D2)/256, 256>>>(evWr, evWi, dWvT);

    k_sal1<<<BB*LL, 128>>>(z, salWr, salWi);
    k_sal2<<<(BB*LL)/256, 256>>>(bias, nov, out_s);
    k_scan<<<BB, 1024>>>(slotm, out_m);
    k_pool<<<BB*SS, 256>>>(z);
    k_proj<<<BB*SS, 256>>>(slotk, slotv, out_k, out_v);
    k_C<<<BB*SS, 256>>>(out_k);

    size_t smem_bytes = (size_t)SM_TOTAL_F * sizeof(float);
    cudaFuncSetAttribute(k_big, cudaFuncAttributeMaxDynamicSharedMemorySize, (int)smem_bytes);

    dim3 grid6(LL/32, BB);
    k_big<<<grid6, 256, smem_bytes>>>(z, out_v, out_m, gamma, out_o);
}

// round 16
// speedup vs baseline: 1.5372x; 1.5372x over previous
#include <cuda_runtime.h>
#include <cuda_bf16.h>
#include <math.h>
#include <float.h>

#define BB 4
#define LL 4096
#define DD 256
#define SS 32
#define TOPK 8
#define D2 512   // 2*DD (interleaved real/imag)

// ---------------- scratch (__device__ globals; no allocation allowed) ----------------
__device__ __align__(256) float  g_phase[BB*LL];
__device__ __align__(256) float  g_avgmag[BB*LL];
__device__ __align__(256) float  g_sal[BB*LL];
__device__ __align__(256) int    g_spst[BB*SS];
__device__ __align__(256) int    g_spen[BB*SS];
__device__ __align__(256) float  g_event[BB*SS*D2];
__device__ __align__(256) double g_kmag[BB*SS];
__device__ __align__(256) float  g_Cf[(size_t)BB*D2*SS];  // [b][j][s] fp32 (computed in fp64)
__device__ __align__(256) float  g_WqT[D2*D2];   // fp32 packed, transposed: [j][o]
__device__ __align__(256) float  g_WqTf[D2*D2];  // tf32-rounded copy (k_big GEMM only)
__device__ __align__(256) float  g_WkT[D2*D2];
__device__ __align__(256) float  g_WvT[D2*D2];

__device__ __forceinline__ float to_tf32(float x) {
    unsigned u;
    asm("cvt.rna.tf32.f32 %0, %1;" : "=r"(u) : "f"(x));
    return __uint_as_float(u);
}

// ---------------- K0: pack complex weight; COALESCED writes ----------------
__global__ void k_pack(const float* __restrict__ wr, const float* __restrict__ wi,
                       float* __restrict__ dstT, float* __restrict__ dstTf) {
    int idx = blockIdx.x * blockDim.x + threadIdx.x;   // 512*512 total
    int j = idx >> 9, o = idx & 511;                   // consecutive threads vary o
    int d = o >> 1, cr = o & 1, e = j >> 1, ci = j & 1;
    float R = wr[d*DD + e], I = wi[d*DD + e];
    float w = (cr == 0) ? ((ci == 0) ? R : -I)
                        : ((ci == 0) ? I :  R);
    dstT[(size_t)j * D2 + o] = w;
    if (dstTf) dstTf[(size_t)j * D2 + o] = to_tf32(w);
}

// ---------------- K1: salience dot (fp64) + avg magnitude (sqrtf, fp64 accum) --------
__global__ void k_sal1(const float* __restrict__ z, const float* __restrict__ swr,
                       const float* __restrict__ swi) {
    int p = blockIdx.x, t = threadIdx.x;   // 128 threads
    const float* zp = z + (size_t)p * D2;
    double orr = 0.0, oii = 0.0, mg = 0.0;
    for (int d = t; d < DD; d += 128) {
        float zr = zp[2*d], zi = zp[2*d+1];
        float a = swr[d], b = swi[d];
        orr += (double)zr*a - (double)zi*b;
        oii += (double)zr*b + (double)zi*a;
        mg  += (double)sqrtf(zr*zr + zi*zi);
    }
    __shared__ double s0[128], s1[128], s2[128];
    s0[t] = orr; s1[t] = oii; s2[t] = mg; __syncthreads();
    for (int off = 64; off; off >>= 1) {
        if (t < off) { s0[t] += s0[t+off]; s1[t] += s1[t+off]; s2[t] += s2[t+off]; }
        __syncthreads();
    }
    if (t == 0) {
        g_phase[p]  = (float)sqrt(s0[0]*s0[0] + s1[0]*s1[0]);
        g_avgmag[p] = (float)(s2[0] * (1.0/256.0));
    }
}

// ---------------- K2: local mean (5-tap, zero-pad) + sigmoid ----------------
__global__ void k_sal2(const float* __restrict__ bias, const float* __restrict__ nov,
                       float* __restrict__ out_sal) {
    int p = blockIdx.x * blockDim.x + threadIdx.x;
    if (p >= BB*LL) return;
    int b = p >> 12, l = p & (LL-1);
    double lm = 0.0;
    #pragma unroll
    for (int j = -2; j <= 2; j++) {
        int q = l + j;
        if (q >= 0 && q < LL) lm += (double)g_avgmag[(b << 12) + q];
    }
    lm *= 0.2;
    double x = (double)g_phase[p] + ((double)g_avgmag[p] - lm) * (double)nov[0] + (double)bias[0];
    float s = (float)(1.0 / (1.0 + exp(-x)));
    g_sal[p] = s;
    out_sal[p] = s;
}

// ---------------- K3: per-batch span scan (exact cumsum of starts) ----------------
__global__ void k_scan(const float* __restrict__ slot_mask, float* __restrict__ out_mask) {
    int b = blockIdx.x, t = threadIdx.x;   // 1024 threads
    __shared__ int sA[LL];
    __shared__ int sP[1024];
    __shared__ int s_n;
    if (t < SS) { g_spst[b*SS + t] = -1; g_spen[b*SS + t] = -1; }
    const float* sb = g_sal + b * LL;
    for (int i = 0; i < 4; i++) { int l = t*4 + i; sA[l] = (sb[l] > 0.5f); }
    __syncthreads();
    int part = 0;
    for (int i = 0; i < 4; i++) {
        int l = t*4 + i;
        int a = sA[l], pr = l ? sA[l-1] : 0;
        part += (a && !pr);
    }
    sP[t] = part; __syncthreads();
    for (int off = 1; off < 1024; off <<= 1) {
        int v = (t >= off) ? sP[t - off] : 0;
        __syncthreads();
        sP[t] += v;
        __syncthreads();
    }
    int run = sP[t] - part;   // exclusive prefix of start count
    for (int i = 0; i < 4; i++) {
        int l = t*4 + i;
        int a = sA[l], pr = l ? sA[l-1] : 0;
        int st = (a && !pr);
        if (st) run++;
        int si = run - 1;
        if (a && si >= 0 && si < SS) {
            if (st) g_spst[b*SS + si] = l;
            int nx = (l < LL-1) ? sA[l+1] : 0;
            if (!nx) g_spen[b*SS + si] = l + 1;
        }
    }
    __syncthreads();
    if (t == 0) s_n = sP[1023];
    __syncthreads();
    if (t < SS) {
        int n = s_n; if (n > SS) n = SS;
        float ev = (t < n) ? 1.f : 0.f;
        out_mask[b*SS + t] = fminf(slot_mask[b*SS + t] + ev, 1.f);
    }
}

// ---------------- K4: salience-weighted pooling per span (fp64 accum) ----------------
__global__ void k_pool(const float* __restrict__ z) {
    int blk = blockIdx.x;            // B*S
    int b = blk >> 5, t = threadIdx.x;   // 256 threads
    int st = g_spst[blk];
    if (st < 0) return;
    int en = g_spen[blk];
    const float* sb = g_sal + b * LL;
    double a0 = 0.0, a1 = 0.0, ws = 0.0;
    for (int l = st; l < en; l++) {
        double w = (double)sb[l];
        const float* zp = z + ((size_t)(b*LL + l)) * D2;
        a0 += w * (double)zp[t];
        a1 += w * (double)zp[t + 256];
        ws += w;
    }
    double inv = 1.0 / fmax(ws, 1e-8);
    g_event[(size_t)blk*D2 + t]       = (float)(a0 * inv);
    g_event[(size_t)blk*D2 + t + 256] = (float)(a1 * inv);
}

// ---------------- K5: event projections, split keys/values (fp64) + k_mag ------------
// grid = 256: blocks 0..127 -> keys (+kmag), 128..255 -> values
__global__ void k_proj(const float* __restrict__ slotk, const float* __restrict__ slotv,
                       float* __restrict__ outk, float* __restrict__ outv) {
    int blk = blockIdx.x;
    int which = blk >> 7;            // 0 = keys, 1 = values
    int sl = blk & 127;              // b*SS+s
    int t = threadIdx.x;             // 256 threads
    __shared__ float  ev[D2];
    __shared__ double red[256];
    bool valid = (g_spst[sl] >= 0);
    if (valid) {
        ev[t]       = g_event[(size_t)sl*D2 + t];
        ev[t + 256] = g_event[(size_t)sl*D2 + t + 256];
    }
    __syncthreads();
    const float* W   = which ? g_WvT : g_WkT;
    const float* src = which ? slotv : slotk;
    float* dst       = which ? outv  : outk;
    float o1, o2;
    if (valid) {
        double a0 = 0.0, a1 = 0.0, b0 = 0.0, b1 = 0.0;
        for (int j = 0; j < D2; j += 2) {
            double e0 = (double)ev[j], e1 = (double)ev[j+1];
            const float* w0 = W + (size_t)j * D2;
            const float* w1 = W + (size_t)(j+1) * D2;
            a0 += e0 * (double)w0[t];       a1 += e1 * (double)w1[t];
            b0 += e0 * (double)w0[t + 256]; b1 += e1 * (double)w1[t + 256];
        }
        o1 = (float)(a0 + a1); o2 = (float)(b0 + b1);
    } else {
        o1 = src[(size_t)sl*D2 + t]; o2 = src[(size_t)sl*D2 + t + 256];
    }
    dst[(size_t)sl*D2 + t] = o1; dst[(size_t)sl*D2 + t + 256] = o2;
    if (which == 0) {
        red[t] = (double)o1*o1 + (double)o2*o2; __syncthreads();
        for (int off = 128; off; off >>= 1) {
            if (t < off) red[t] += red[t + off];
            __syncthreads();
        }
        if (t == 0) g_kmag[sl] = sqrt(red[0] + 1e-8);
    }
}

// ---------------- K5b: C[b][j][s] = sum_o WqT[j][o] * newk[b][s][o] (fp64 -> fp32 store) ----
__global__ void k_C(const float* __restrict__ newk) {
    int blk = blockIdx.x;            // b*SS + s
    int b = blk >> 5, s = blk & 31, t = threadIdx.x;   // 256 threads
    __shared__ float ks[D2];
    ks[t]       = newk[(size_t)blk*D2 + t];
    ks[t + 256] = newk[(size_t)blk*D2 + t + 256];
    __syncthreads();
    #pragma unroll
    for (int jj = 0; jj < 2; jj++) {
        int j = t + jj*256;
        const float* wrow = g_WqT + (size_t)j * D2;
        double a0 = 0.0, a1 = 0.0, a2 = 0.0, a3 = 0.0;
        for (int o = 0; o < D2; o += 4) {
            a0 += (double)wrow[o+0] * (double)ks[o+0];
            a1 += (double)wrow[o+1] * (double)ks[o+1];
            a2 += (double)wrow[o+2] * (double)ks[o+2];
            a3 += (double)wrow[o+3] * (double)ks[o+3];
        }
        g_Cf[((size_t)b*D2 + j)*SS + s] = (float)((a0+a1)+(a2+a3));
    }
}

// ---------------- K6: tf32-mma qmag-GEMM + shared-load chunked-dot attention + RMS ----
// dyn smem layout (floats):
//   As   [16][40]    @ 0
//   Bs   [16][520]   @ 640
//   psum [32][17]    @ 8960
//   Vs   [32][516]   @ 9504    (stride 516 -> 16B-aligned rows for float4)
//   gam  [256]       @ 26016
//   mask [32]        @ 26272
#define SM_AS    0
#define SM_BS    640
#define SM_PS    8960
#define SM_VS    9504
#define SM_GAM   26016
#define SM_MSK   26272
#define SM_TOTAL_F 26304

__global__ __launch_bounds__(256, 2) void k_big(const float* __restrict__ z,
                      const float* __restrict__ newv,
                      const float* __restrict__ newmask,
                      const float* __restrict__ gamma, float* __restrict__ out) {
    extern __shared__ float sm[];
    float* As = sm + SM_AS;       // [16][40]
    float* Bs = sm + SM_BS;       // [16][520]
    float* psum = sm + SM_PS;     // [32][17]
    float* Vs = sm + SM_VS;       // [32][516]
    float* gam_s  = sm + SM_GAM;
    float* mask_s = sm + SM_MSK;
    __shared__ double km_s[SS];

    int t = threadIdx.x;                 // 256
    int b = blockIdx.y;
    int row0 = blockIdx.x * 32;          // within batch
    size_t zbase = ((size_t)b*LL + row0) * D2;

    // stage values (float4) / mask / kmag / gamma
    #pragma unroll
    for (int i = 0; i < 16; i++) {
        int e4 = t + i*256;              // 4096 float4
        int s = e4 >> 7, j4 = e4 & 127;
        float4 v = *(const float4*)(newv + ((size_t)b*SS + s)*D2 + j4*4);
        *(float4*)&Vs[s*516 + j4*4] = v;
    }
    if (t < SS) { km_s[t] = g_kmag[b*SS + t]; mask_s[t] = newmask[b*SS + t]; }
    gam_s[t] = gamma[t];

    // ---- GEMM (tf32 tensor cores): Q[32 x 512] = Z @ WqTf; only q_mag uses it.
    int lane = t & 31, w = t >> 5;
    int qrow = lane >> 2, tig = lane & 3;
    int rt16 = (w & 1) * 16;
    int cbase = (w >> 1) * 128;

    float c[16][4];
    #pragma unroll
    for (int nt = 0; nt < 16; nt++) {
        c[nt][0] = 0.f; c[nt][1] = 0.f; c[nt][2] = 0.f; c[nt][3] = 0.f;
    }

    for (int k0 = 0; k0 < D2; k0 += 16) {
        __syncthreads();
        #pragma unroll
        for (int i = 0; i < 2; i++) {
            int e = t + i*256; int kk = e & 15, r = e >> 4;
            As[kk*40 + r] = to_tf32(z[zbase + (size_t)r*D2 + k0 + kk]);
        }
        #pragma unroll
        for (int i = 0; i < 8; i++) {
            int e4 = t + i*256;              // 2048 float4 = 16k x 128
            int kk = e4 >> 7, o4 = e4 & 127;
            float4 v = *(const float4*)(g_WqTf + (size_t)(k0 + kk)*D2 + o4*4);
            *(float4*)&Bs[kk*520 + o4*4] = v;
        }
        __syncthreads();
        #pragma unroll
        for (int ks = 0; ks < 16; ks += 8) {
            int kb = ks + tig;
            float a0 = As[kb*40 + rt16 + qrow];
            float a1 = As[kb*40 + rt16 + qrow + 8];
            float a2 = As[(kb+4)*40 + rt16 + qrow];
            float a3 = As[(kb+4)*40 + rt16 + qrow + 8];
            unsigned ua0 = __float_as_uint(a0), ua1 = __float_as_uint(a1);
            unsigned ua2 = __float_as_uint(a2), ua3 = __float_as_uint(a3);
            #pragma unroll
            for (int nt = 0; nt < 16; nt++) {
                float b0 = Bs[kb*520 + cbase + nt*8 + qrow];
                float b1 = Bs[(kb+4)*520 + cbase + nt*8 + qrow];
                asm volatile(
                    "mma.sync.aligned.m16n8k8.row.col.f32.tf32.tf32.f32 "
                    "{%0,%1,%2,%3}, {%4,%5,%6,%7}, {%8,%9}, {%0,%1,%2,%3};"
                    : "+f"(c[nt][0]), "+f"(c[nt][1]), "+f"(c[nt][2]), "+f"(c[nt][3])
                    : "r"(ua0), "r"(ua1), "r"(ua2), "r"(ua3),
                      "r"(__float_as_uint(b0)), "r"(__float_as_uint(b1)));
            }
        }
    }
    __syncthreads();

    // ---- per-thread row sums-of-squares from C fragments ----
    {
        float plo = 0.f, phi = 0.f;
        #pragma unroll
        for (int nt = 0; nt < 16; nt++) {
            plo += c[nt][0]*c[nt][0] + c[nt][1]*c[nt][1];
            phi += c[nt][2]*c[nt][2] + c[nt][3]*c[nt][3];
        }
        int slot = (w >> 1) * 4 + tig;      // 0..15
        psum[(rt16 + qrow)*17 + slot]     = plo;
        psum[(rt16 + qrow + 8)*17 + slot] = phi;
    }
    __syncthreads();

    // ---- attention: warp w owns rows w*4..w*4+3; slot = lane ----
    const float* Cb = g_Cf + (size_t)b*D2*SS;   // [j][s] fp32

    const float* zr0 = z + ((size_t)b*LL + row0 + w*4 + 0) * D2;
    const float* zr1 = z + ((size_t)b*LL + row0 + w*4 + 1) * D2;
    const float* zr2 = z + ((size_t)b*LL + row0 + w*4 + 2) * D2;
    const float* zr3 = z + ((size_t)b*LL + row0 + w*4 + 3) * D2;
    double dot_[4] = {0.0, 0.0, 0.0, 0.0};
    for (int j0 = 0; j0 < D2; j0 += 16) {
        float p0 = 0.f, p1 = 0.f, p2 = 0.f, p3 = 0.f;
        #pragma unroll
        for (int jj = 0; jj < 16; jj++) {
            int j = j0 + jj;
            float cv = Cb[(size_t)j*SS + lane];
            p0 += zr0[j]*cv;
            p1 += zr1[j]*cv;
            p2 += zr2[j]*cv;
            p3 += zr3[j]*cv;
        }
        dot_[0] += (double)p0;
        dot_[1] += (double)p1;
        dot_[2] += (double)p2;
        dot_[3] += (double)p3;
    }

    for (int ri = 0; ri < 4; ri++) {
        int r = w*4 + ri;
        float qsq = 0.f;
        #pragma unroll
        for (int i = 0; i < 16; i++) qsq += psum[r*17 + i];
        double qmag = sqrt((double)qsq + 1e-8);
        float scored = (float)(dot_[ri] / (qmag * km_s[lane] + 1e-8));
        if (mask_s[lane] == 0.f) scored = -1e9f;
        // top-8 in fp32 (tie -> lower index, matching lax.top_k)
        float sc = scored;
        float bv_[TOPK]; int bi_[TOPK];
        #pragma unroll
        for (int k = 0; k < TOPK; k++) {
            float vv = sc; int vi = lane;
            #pragma unroll
            for (int off = 16; off; off >>= 1) {
                float ov = __shfl_xor_sync(0xffffffffu, vv, off);
                int   oi = __shfl_xor_sync(0xffffffffu, vi, off);
                if (ov > vv || (ov == vv && oi < vi)) { vv = ov; vi = oi; }
            }
            bv_[k] = vv; bi_[k] = vi;
            if (lane == vi) sc = -3.4e38f;
        }
        // softmax over the 8 (fp32)
        float m = bv_[0], se = 0.f, wn[TOPK];
        #pragma unroll
        for (int k = 0; k < TOPK; k++) { float e = expf(bv_[k] - m); wn[k] = e; se += e; }
        float inv = 1.f / se;
        #pragma unroll
        for (int k = 0; k < TOPK; k++) wn[k] *= inv;
        // retrieved + RMS norm
        float ov_[16]; float m2 = 0.f;
        #pragma unroll
        for (int tt = 0; tt < 16; tt++) {
            int j = lane + tt*32;
            float acc = 0.f;
            #pragma unroll
            for (int k = 0; k < TOPK; k++) acc += wn[k] * Vs[bi_[k]*516 + j];
            ov_[tt] = acc; m2 += acc*acc;
        }
        #pragma unroll
        for (int off = 16; off; off >>= 1) m2 += __shfl_xor_sync(0xffffffffu, m2, off);
        float scale = rsqrtf(m2 * (1.f/256.f) + 1e-8f);
        size_t ob = ((size_t)b*LL + row0 + r) * D2;
        #pragma unroll
        for (int tt = 0; tt < 16; tt++) {
            int j = lane + tt*32;
            out[ob + j] = ov_[tt] * gam_s[j >> 1] * scale;
        }
    }
}

// ---------------- launch ----------------
extern "C" void kernel_launch(void* const* d_in, const int* in_sizes, int n_in,
                              void* d_out, int out_size) {
    const float* z      = (const float*)d_in[0];
    const float* slotk  = (const float*)d_in[1];
    const float* slotv  = (const float*)d_in[2];
    const float* slotm  = (const float*)d_in[3];
    const float* salWr  = (const float*)d_in[4];
    const float* salWi  = (const float*)d_in[5];
    const float* bias   = (const float*)d_in[6];
    const float* nov    = (const float*)d_in[7];
    const float* ekWr   = (const float*)d_in[8];
    const float* ekWi   = (const float*)d_in[9];
    const float* evWr   = (const float*)d_in[10];
    const float* evWi   = (const float*)d_in[11];
    const float* rqWr   = (const float*)d_in[12];
    const float* rqWi   = (const float*)d_in[13];
    const float* gamma  = (const float*)d_in[14];

    float* out   = (float*)d_out;
    float* out_o = out;                               // [4,4096,256,2]
    float* out_k = out + (size_t)BB*LL*D2;            // [4,32,256,2]
    float* out_v = out_k + (size_t)BB*SS*D2;
    float* out_m = out_v + (size_t)BB*SS*D2;          // [4,32]
    float* out_s = out_m + (size_t)BB*SS;             // [4,4096]

    float *dWqT, *dWqTf, *dWkT, *dWvT;
    cudaGetSymbolAddress((void**)&dWqT,  g_WqT);
    cudaGetSymbolAddress((void**)&dWqTf, g_WqTf);
    cudaGetSymbolAddress((void**)&dWkT,  g_WkT);
    cudaGetSymbolAddress((void**)&dWvT,  g_WvT);

    k_pack<<<(D2*D2)/256, 256>>>(rqWr, rqWi, dWqT, dWqTf);
    k_pack<<<(D2*D2)/256, 256>>>(ekWr, ekWi, dWkT, (float*)nullptr);
    k_pack<<<(D2*D2)/256, 256>>>(evWr, evWi, dWvT, (float*)nullptr);

    k_sal1<<<BB*LL, 128>>>(z, salWr, salWi);
    k_sal2<<<(BB*LL)/256, 256>>>(bias, nov, out_s);
    k_scan<<<BB, 1024>>>(slotm, out_m);
    k_pool<<<BB*SS, 256>>>(z);
    k_proj<<<2*BB*SS, 256>>>(slotk, slotv, out_k, out_v);
    k_C<<<BB*SS, 256>>>(out_k);

    size_t smem_bytes = (size_t)SM_TOTAL_F * sizeof(float);
    cudaFuncSetAttribute(k_big, cudaFuncAttributeMaxDynamicSharedMemorySize, (int)smem_bytes);

    dim3 grid6(LL/32, BB);
    k_big<<<grid6, 256, smem_bytes>>>(z, out_v, out_m, gamma, out_o);
}

// round 17
// speedup vs baseline: 1.8881x; 1.2283x over previous
#include <cuda_runtime.h>
#include <cuda_bf16.h>
#include <math.h>
#include <float.h>

#define BB 4
#define LL 4096
#define DD 256
#define SS 32
#define TOPK 8
#define D2 512   // 2*DD (interleaved real/imag)

// ---------------- scratch (__device__ globals; no allocation allowed) ----------------
__device__ __align__(256) float  g_phase[BB*LL];
__device__ __align__(256) float  g_avgmag[BB*LL];
__device__ __align__(256) float  g_sal[BB*LL];
__device__ __align__(256) int    g_spst[BB*SS];
__device__ __align__(256) int    g_spen[BB*SS];
__device__ __align__(256) float  g_event[BB*SS*D2];
__device__ __align__(256) double g_kmag[BB*SS];
__device__ __align__(256) float  g_Cf[(size_t)BB*D2*SS];  // [b][j][s] fp32 (computed in fp64)
__device__ __align__(256) float  g_WqT[D2*D2];   // fp32 packed, transposed: [j][o]
__device__ __align__(256) float  g_WqTf[D2*D2];  // tf32-rounded copy (k_big GEMM only)
__device__ __align__(256) float  g_WkT[D2*D2];
__device__ __align__(256) float  g_WvT[D2*D2];

__device__ __forceinline__ float to_tf32(float x) {
    unsigned u;
    asm("cvt.rna.tf32.f32 %0, %1;" : "=r"(u) : "f"(x));
    return __uint_as_float(u);
}

// ---------------- K0: pack complex weight; COALESCED writes ----------------
__global__ void k_pack(const float* __restrict__ wr, const float* __restrict__ wi,
                       float* __restrict__ dstT, float* __restrict__ dstTf) {
    int idx = blockIdx.x * blockDim.x + threadIdx.x;   // 512*512 total
    int j = idx >> 9, o = idx & 511;                   // consecutive threads vary o
    int d = o >> 1, cr = o & 1, e = j >> 1, ci = j & 1;
    float R = wr[d*DD + e], I = wi[d*DD + e];
    float w = (cr == 0) ? ((ci == 0) ? R : -I)
                        : ((ci == 0) ? I :  R);
    dstT[(size_t)j * D2 + o] = w;
    if (dstTf) dstTf[(size_t)j * D2 + o] = to_tf32(w);
}

// ---------------- K1: salience dot + avg magnitude; warp per position, float4 --------
__global__ void k_sal1(const float* __restrict__ z, const float* __restrict__ swr,
                       const float* __restrict__ swi) {
    int t = threadIdx.x, lane = t & 31, w = t >> 5;   // 256 threads = 8 warps
    int p = blockIdx.x * 8 + w;
    const float4* zp = (const float4*)(z + (size_t)p * D2);   // 128 float4
    const float2* wr2 = (const float2*)swr;
    const float2* wi2 = (const float2*)swi;
    double orr = 0.0, oii = 0.0, mg = 0.0;
    #pragma unroll
    for (int k = 0; k < 4; k++) {
        int i = lane + k*32;            // float4 i holds complex 2i and 2i+1
        float4 f = zp[i];
        float2 a = wr2[i];
        float2 bq = wi2[i];
        orr += (double)f.x*a.x - (double)f.y*bq.x;
        oii += (double)f.x*bq.x + (double)f.y*a.x;
        orr += (double)f.z*a.y - (double)f.w*bq.y;
        oii += (double)f.z*bq.y + (double)f.w*a.y;
        mg  += (double)sqrtf(f.x*f.x + f.y*f.y);
        mg  += (double)sqrtf(f.z*f.z + f.w*f.w);
    }
    #pragma unroll
    for (int off = 16; off; off >>= 1) {
        orr += __shfl_xor_sync(0xffffffffu, orr, off);
        oii += __shfl_xor_sync(0xffffffffu, oii, off);
        mg  += __shfl_xor_sync(0xffffffffu, mg,  off);
    }
    if (lane == 0) {
        g_phase[p]  = (float)sqrt(orr*orr + oii*oii);
        g_avgmag[p] = (float)(mg * (1.0/256.0));
    }
}

// ---------------- K2: local mean (5-tap, zero-pad) + sigmoid ----------------
__global__ void k_sal2(const float* __restrict__ bias, const float* __restrict__ nov,
                       float* __restrict__ out_sal) {
    int p = blockIdx.x * blockDim.x + threadIdx.x;
    if (p >= BB*LL) return;
    int b = p >> 12, l = p & (LL-1);
    double lm = 0.0;
    #pragma unroll
    for (int j = -2; j <= 2; j++) {
        int q = l + j;
        if (q >= 0 && q < LL) lm += (double)g_avgmag[(b << 12) + q];
    }
    lm *= 0.2;
    double x = (double)g_phase[p] + ((double)g_avgmag[p] - lm) * (double)nov[0] + (double)bias[0];
    float s = (float)(1.0 / (1.0 + exp(-x)));
    g_sal[p] = s;
    out_sal[p] = s;
}

// ---------------- K3: per-batch span scan (exact cumsum of starts) ----------------
__global__ void k_scan(const float* __restrict__ slot_mask, float* __restrict__ out_mask) {
    int b = blockIdx.x, t = threadIdx.x;   // 1024 threads
    __shared__ int sA[LL];
    __shared__ int sP[1024];
    __shared__ int s_n;
    if (t < SS) { g_spst[b*SS + t] = -1; g_spen[b*SS + t] = -1; }
    const float* sb = g_sal + b * LL;
    for (int i = 0; i < 4; i++) { int l = t*4 + i; sA[l] = (sb[l] > 0.5f); }
    __syncthreads();
    int part = 0;
    for (int i = 0; i < 4; i++) {
        int l = t*4 + i;
        int a = sA[l], pr = l ? sA[l-1] : 0;
        part += (a && !pr);
    }
    sP[t] = part; __syncthreads();
    for (int off = 1; off < 1024; off <<= 1) {
        int v = (t >= off) ? sP[t - off] : 0;
        __syncthreads();
        sP[t] += v;
        __syncthreads();
    }
    int run = sP[t] - part;   // exclusive prefix of start count
    for (int i = 0; i < 4; i++) {
        int l = t*4 + i;
        int a = sA[l], pr = l ? sA[l-1] : 0;
        int st = (a && !pr);
        if (st) run++;
        int si = run - 1;
        if (a && si >= 0 && si < SS) {
            if (st) g_spst[b*SS + si] = l;
            int nx = (l < LL-1) ? sA[l+1] : 0;
            if (!nx) g_spen[b*SS + si] = l + 1;
        }
    }
    __syncthreads();
    if (t == 0) s_n = sP[1023];
    __syncthreads();
    if (t < SS) {
        int n = s_n; if (n > SS) n = SS;
        float ev = (t < n) ? 1.f : 0.f;
        out_mask[b*SS + t] = fminf(slot_mask[b*SS + t] + ev, 1.f);
    }
}

// ---------------- K4: salience-weighted pooling per span (fp64 accum) ----------------
__global__ void k_pool(const float* __restrict__ z) {
    int blk = blockIdx.x;            // B*S
    int b = blk >> 5, t = threadIdx.x;   // 256 threads
    int st = g_spst[blk];
    if (st < 0) return;
    int en = g_spen[blk];
    const float* sb = g_sal + b * LL;
    double a0 = 0.0, a1 = 0.0, ws = 0.0;
    for (int l = st; l < en; l++) {
        double w = (double)sb[l];
        const float* zp = z + ((size_t)(b*LL + l)) * D2;
        a0 += w * (double)zp[t];
        a1 += w * (double)zp[t + 256];
        ws += w;
    }
    double inv = 1.0 / fmax(ws, 1e-8);
    g_event[(size_t)blk*D2 + t]       = (float)(a0 * inv);
    g_event[(size_t)blk*D2 + t + 256] = (float)(a1 * inv);
}

// ---------------- K5: event projections, split keys/values; chunked fp32 + fp64 ------
// grid = 256: blocks 0..127 -> keys (+kmag), 128..255 -> values
__global__ void k_proj(const float* __restrict__ slotk, const float* __restrict__ slotv,
                       float* __restrict__ outk, float* __restrict__ outv) {
    int blk = blockIdx.x;
    int which = blk >> 7;            // 0 = keys, 1 = values
    int sl = blk & 127;              // b*SS+s
    int t = threadIdx.x;             // 256 threads
    __shared__ float  ev[D2];
    __shared__ double red[256];
    bool valid = (g_spst[sl] >= 0);
    if (valid) {
        ev[t]       = g_event[(size_t)sl*D2 + t];
        ev[t + 256] = g_event[(size_t)sl*D2 + t + 256];
    }
    __syncthreads();
    const float* W   = which ? g_WvT : g_WkT;
    const float* src = which ? slotv : slotk;
    float* dst       = which ? outv  : outk;
    float o1, o2;
    if (valid) {
        double ad = 0.0, bd = 0.0;
        for (int j0 = 0; j0 < D2; j0 += 16) {
            float pa = 0.f, pb = 0.f;
            #pragma unroll
            for (int jj = 0; jj < 16; jj++) {
                float e = ev[j0 + jj];
                const float* wrow = W + (size_t)(j0 + jj) * D2;
                pa += e * wrow[t];
                pb += e * wrow[t + 256];
            }
            ad += (double)pa; bd += (double)pb;
        }
        o1 = (float)ad; o2 = (float)bd;
    } else {
        o1 = src[(size_t)sl*D2 + t]; o2 = src[(size_t)sl*D2 + t + 256];
    }
    dst[(size_t)sl*D2 + t] = o1; dst[(size_t)sl*D2 + t + 256] = o2;
    if (which == 0) {
        red[t] = (double)o1*o1 + (double)o2*o2; __syncthreads();
        for (int off = 128; off; off >>= 1) {
            if (t < off) red[t] += red[t + off];
            __syncthreads();
        }
        if (t == 0) g_kmag[sl] = sqrt(red[0] + 1e-8);
    }
}

// ---------------- K5b: C[b][j][s] (fp64 -> fp32 store); split j-halves, 256 blocks ----
__global__ void k_C(const float* __restrict__ newk) {
    int blk = blockIdx.x;            // 256 blocks
    int which = blk >> 7;            // j half: 0 -> j=t, 1 -> j=t+256
    int sl = blk & 127;              // b*SS + s
    int b = sl >> 5, s = sl & 31, t = threadIdx.x;   // 256 threads
    __shared__ float ks[D2];
    ks[t]       = newk[(size_t)sl*D2 + t];
    ks[t + 256] = newk[(size_t)sl*D2 + t + 256];
    __syncthreads();
    int j = t + which*256;
    const float* wrow = g_WqT + (size_t)j * D2;
    double a0 = 0.0, a1 = 0.0, a2 = 0.0, a3 = 0.0;
    for (int o = 0; o < D2; o += 4) {
        a0 += (double)wrow[o+0] * (double)ks[o+0];
        a1 += (double)wrow[o+1] * (double)ks[o+1];
        a2 += (double)wrow[o+2] * (double)ks[o+2];
        a3 += (double)wrow[o+3] * (double)ks[o+3];
    }
    g_Cf[((size_t)b*D2 + j)*SS + s] = (float)((a0+a1)+(a2+a3));
}

// ---------------- K6: tf32-mma qmag-GEMM + shared-load chunked-dot attention + RMS ----
// dyn smem layout (floats):
//   As   [16][40]    @ 0
//   Bs   [16][520]   @ 640
//   psum [32][17]    @ 8960
//   Vs   [32][516]   @ 9504    (stride 516 -> 16B-aligned rows for float4)
//   gam  [256]       @ 26016
//   mask [32]        @ 26272
#define SM_AS    0
#define SM_BS    640
#define SM_PS    8960
#define SM_VS    9504
#define SM_GAM   26016
#define SM_MSK   26272
#define SM_TOTAL_F 26304

__global__ __launch_bounds__(256, 2) void k_big(const float* __restrict__ z,
                      const float* __restrict__ newv,
                      const float* __restrict__ newmask,
                      const float* __restrict__ gamma, float* __restrict__ out) {
    extern __shared__ float sm[];
    float* As = sm + SM_AS;       // [16][40]
    float* Bs = sm + SM_BS;       // [16][520]
    float* psum = sm + SM_PS;     // [32][17]
    float* Vs = sm + SM_VS;       // [32][516]
    float* gam_s  = sm + SM_GAM;
    float* mask_s = sm + SM_MSK;
    __shared__ double km_s[SS];

    int t = threadIdx.x;                 // 256
    int b = blockIdx.y;
    int row0 = blockIdx.x * 32;          // within batch
    size_t zbase = ((size_t)b*LL + row0) * D2;

    // stage values (float4) / mask / kmag / gamma
    #pragma unroll
    for (int i = 0; i < 16; i++) {
        int e4 = t + i*256;              // 4096 float4
        int s = e4 >> 7, j4 = e4 & 127;
        float4 v = *(const float4*)(newv + ((size_t)b*SS + s)*D2 + j4*4);
        *(float4*)&Vs[s*516 + j4*4] = v;
    }
    if (t < SS) { km_s[t] = g_kmag[b*SS + t]; mask_s[t] = newmask[b*SS + t]; }
    gam_s[t] = gamma[t];

    // ---- GEMM (tf32 tensor cores): Q[32 x 512] = Z @ WqTf; only q_mag uses it.
    int lane = t & 31, w = t >> 5;
    int qrow = lane >> 2, tig = lane & 3;
    int rt16 = (w & 1) * 16;
    int cbase = (w >> 1) * 128;

    float c[16][4];
    #pragma unroll
    for (int nt = 0; nt < 16; nt++) {
        c[nt][0] = 0.f; c[nt][1] = 0.f; c[nt][2] = 0.f; c[nt][3] = 0.f;
    }

    for (int k0 = 0; k0 < D2; k0 += 16) {
        __syncthreads();
        #pragma unroll
        for (int i = 0; i < 2; i++) {
            int e = t + i*256; int kk = e & 15, r = e >> 4;
            As[kk*40 + r] = to_tf32(z[zbase + (size_t)r*D2 + k0 + kk]);
        }
        #pragma unroll
        for (int i = 0; i < 8; i++) {
            int e4 = t + i*256;              // 2048 float4 = 16k x 128
            int kk = e4 >> 7, o4 = e4 & 127;
            float4 v = *(const float4*)(g_WqTf + (size_t)(k0 + kk)*D2 + o4*4);
            *(float4*)&Bs[kk*520 + o4*4] = v;
        }
        __syncthreads();
        #pragma unroll
        for (int ks = 0; ks < 16; ks += 8) {
            int kb = ks + tig;
            float a0 = As[kb*40 + rt16 + qrow];
            float a1 = As[kb*40 + rt16 + qrow + 8];
            float a2 = As[(kb+4)*40 + rt16 + qrow];
            float a3 = As[(kb+4)*40 + rt16 + qrow + 8];
            unsigned ua0 = __float_as_uint(a0), ua1 = __float_as_uint(a1);
            unsigned ua2 = __float_as_uint(a2), ua3 = __float_as_uint(a3);
            #pragma unroll
            for (int nt = 0; nt < 16; nt++) {
                float b0 = Bs[kb*520 + cbase + nt*8 + qrow];
                float b1 = Bs[(kb+4)*520 + cbase + nt*8 + qrow];
                asm volatile(
                    "mma.sync.aligned.m16n8k8.row.col.f32.tf32.tf32.f32 "
                    "{%0,%1,%2,%3}, {%4,%5,%6,%7}, {%8,%9}, {%0,%1,%2,%3};"
                    : "+f"(c[nt][0]), "+f"(c[nt][1]), "+f"(c[nt][2]), "+f"(c[nt][3])
                    : "r"(ua0), "r"(ua1), "r"(ua2), "r"(ua3),
                      "r"(__float_as_uint(b0)), "r"(__float_as_uint(b1)));
            }
        }
    }
    __syncthreads();

    // ---- per-thread row sums-of-squares from C fragments ----
    {
        float plo = 0.f, phi = 0.f;
        #pragma unroll
        for (int nt = 0; nt < 16; nt++) {
            plo += c[nt][0]*c[nt][0] + c[nt][1]*c[nt][1];
            phi += c[nt][2]*c[nt][2] + c[nt][3]*c[nt][3];
        }
        int slot = (w >> 1) * 4 + tig;      // 0..15
        psum[(rt16 + qrow)*17 + slot]     = plo;
        psum[(rt16 + qrow + 8)*17 + slot] = phi;
    }
    __syncthreads();

    // ---- attention: warp w owns rows w*4..w*4+3; slot = lane ----
    const float* Cb = g_Cf + (size_t)b*D2*SS;   // [j][s] fp32

    const float* zr0 = z + ((size_t)b*LL + row0 + w*4 + 0) * D2;
    const float* zr1 = z + ((size_t)b*LL + row0 + w*4 + 1) * D2;
    const float* zr2 = z + ((size_t)b*LL + row0 + w*4 + 2) * D2;
    const float* zr3 = z + ((size_t)b*LL + row0 + w*4 + 3) * D2;
    double dot_[4] = {0.0, 0.0, 0.0, 0.0};
    for (int j0 = 0; j0 < D2; j0 += 16) {
        float p0 = 0.f, p1 = 0.f, p2 = 0.f, p3 = 0.f;
        #pragma unroll
        for (int q4 = 0; q4 < 4; q4++) {
            int jb = j0 + q4*4;
            float4 z0 = *(const float4*)(zr0 + jb);
            float4 z1 = *(const float4*)(zr1 + jb);
            float4 z2 = *(const float4*)(zr2 + jb);
            float4 z3 = *(const float4*)(zr3 + jb);
            float cv0 = Cb[(size_t)(jb+0)*SS + lane];
            float cv1 = Cb[(size_t)(jb+1)*SS + lane];
            float cv2 = Cb[(size_t)(jb+2)*SS + lane];
            float cv3 = Cb[(size_t)(jb+3)*SS + lane];
            p0 += z0.x*cv0; p0 += z0.y*cv1; p0 += z0.z*cv2; p0 += z0.w*cv3;
            p1 += z1.x*cv0; p1 += z1.y*cv1; p1 += z1.z*cv2; p1 += z1.w*cv3;
            p2 += z2.x*cv0; p2 += z2.y*cv1; p2 += z2.z*cv2; p2 += z2.w*cv3;
            p3 += z3.x*cv0; p3 += z3.y*cv1; p3 += z3.z*cv2; p3 += z3.w*cv3;
        }
        dot_[0] += (double)p0;
        dot_[1] += (double)p1;
        dot_[2] += (double)p2;
        dot_[3] += (double)p3;
    }

    for (int ri = 0; ri < 4; ri++) {
        int r = w*4 + ri;
        float qsq = 0.f;
        #pragma unroll
        for (int i = 0; i < 16; i++) qsq += psum[r*17 + i];
        double qmag = sqrt((double)qsq + 1e-8);
        float scored = (float)(dot_[ri] / (qmag * km_s[lane] + 1e-8));
        if (mask_s[lane] == 0.f) scored = -1e9f;
        // top-8 in fp32 (tie -> lower index, matching lax.top_k)
        float sc = scored;
        float bv_[TOPK]; int bi_[TOPK];
        #pragma unroll
        for (int k = 0; k < TOPK; k++) {
            float vv = sc; int vi = lane;
            #pragma unroll
            for (int off = 16; off; off >>= 1) {
                float ov = __shfl_xor_sync(0xffffffffu, vv, off);
                int   oi = __shfl_xor_sync(0xffffffffu, vi, off);
                if (ov > vv || (ov == vv && oi < vi)) { vv = ov; vi = oi; }
            }
            bv_[k] = vv; bi_[k] = vi;
            if (lane == vi) sc = -3.4e38f;
        }
        // softmax over the 8 (fp32)
        float m = bv_[0], se = 0.f, wn[TOPK];
        #pragma unroll
        for (int k = 0; k < TOPK; k++) { float e = expf(bv_[k] - m); wn[k] = e; se += e; }
        float inv = 1.f / se;
        #pragma unroll
        for (int k = 0; k < TOPK; k++) wn[k] *= inv;
        // retrieved + RMS norm
        float ov_[16]; float m2 = 0.f;
        #pragma unroll
        for (int tt = 0; tt < 16; tt++) {
            int j = lane + tt*32;
            float acc = 0.f;
            #pragma unroll
            for (int k = 0; k < TOPK; k++) acc += wn[k] * Vs[bi_[k]*516 + j];
            ov_[tt] = acc; m2 += acc*acc;
        }
        #pragma unroll
        for (int off = 16; off; off >>= 1) m2 += __shfl_xor_sync(0xffffffffu, m2, off);
        float scale = rsqrtf(m2 * (1.f/256.f) + 1e-8f);
        size_t ob = ((size_t)b*LL + row0 + r) * D2;
        #pragma unroll
        for (int tt = 0; tt < 16; tt++) {
            int j = lane + tt*32;
            out[ob + j] = ov_[tt] * gam_s[j >> 1] * scale;
        }
    }
}

// ---------------- launch ----------------
extern "C" void kernel_launch(void* const* d_in, const int* in_sizes, int n_in,
                              void* d_out, int out_size) {
    const float* z      = (const float*)d_in[0];
    const float* slotk  = (const float*)d_in[1];
    const float* slotv  = (const float*)d_in[2];
    const float* slotm  = (const float*)d_in[3];
    const float* salWr  = (const float*)d_in[4];
    const float* salWi  = (const float*)d_in[5];
    const float* bias   = (const float*)d_in[6];
    const float* nov    = (const float*)d_in[7];
    const float* ekWr   = (const float*)d_in[8];
    const float* ekWi   = (const float*)d_in[9];
    const float* evWr   = (const float*)d_in[10];
    const float* evWi   = (const float*)d_in[11];
    const float* rqWr   = (const float*)d_in[12];
    const float* rqWi   = (const float*)d_in[13];
    const float* gamma  = (const float*)d_in[14];

    float* out   = (float*)d_out;
    float* out_o = out;                               // [4,4096,256,2]
    float* out_k = out + (size_t)BB*LL*D2;            // [4,32,256,2]
    float* out_v = out_k + (size_t)BB*SS*D2;
    float* out_m = out_v + (size_t)BB*SS*D2;          // [4,32]
    float* out_s = out_m + (size_t)BB*SS;             // [4,4096]

    float *dWqT, *dWqTf, *dWkT, *dWvT;
    cudaGetSymbolAddress((void**)&dWqT,  g_WqT);
    cudaGetSymbolAddress((void**)&dWqTf, g_WqTf);
    cudaGetSymbolAddress((void**)&dWkT,  g_WkT);
    cudaGetSymbolAddress((void**)&dWvT,  g_WvT);

    k_pack<<<(D2*D2)/256, 256>>>(rqWr, rqWi, dWqT, dWqTf);
    k_pack<<<(D2*D2)/256, 256>>>(ekWr, ekWi, dWkT, (float*)nullptr);
    k_pack<<<(D2*D2)/256, 256>>>(evWr, evWi, dWvT, (float*)nullptr);

    k_sal1<<<(BB*LL)/8, 256>>>(z, salWr, salWi);
    k_sal2<<<(BB*LL)/256, 256>>>(bias, nov, out_s);
    k_scan<<<BB, 1024>>>(slotm, out_m);
    k_pool<<<BB*SS, 256>>>(z);
    k_proj<<<2*BB*SS, 256>>>(slotk, slotv, out_k, out_v);
    k_C<<<2*BB*SS, 256>>>(out_k);

    size_t smem_bytes = (size_t)SM_TOTAL_F * sizeof(float);
    cudaFuncSetAttribute(k_big, cudaFuncAttributeMaxDynamicSharedMemorySize, (int)smem_bytes);

    dim3 grid6(LL/32, BB);
    k_big<<<grid6, 256, smem_bytes>>>(z, out_v, out_m, gamma, out_o);
}